// round 12
// baseline (speedup 1.0000x reference)
#include <cuda_runtime.h>
#include <cuda_fp16.h>
#include <cstdint>

#define DEF 256
#define NF  4096   // DEF * HEAD
#define BSZ 4096

// f16 scratch
__device__ __half g_abf[2][(size_t)BSZ * DEF];   // drug/protein f16
__device__ __half g_wbf[2][(size_t)DEF * NF];    // W in ORIGINAL [k][n] layout, f16 (W_d pre-scaled by 1/16)
__device__ __half g_att[2][(size_t)BSZ * NF];    // relu activations f16 (drug side pre-scaled)

// ---------------------------------------------------------------------------
// helpers
// ---------------------------------------------------------------------------
__device__ __forceinline__ float tanh_fast(float x) {
    float y;
    asm("tanh.approx.f32 %0, %1;" : "=f"(y) : "f"(x));
    return y;
}
__device__ __forceinline__ uint32_t tanh_h2u(uint32_t v) {
    uint32_t r;
    asm("tanh.approx.f16x2 %0, %1;" : "=r"(r) : "r"(v));
    return r;
}
__device__ __forceinline__ uint32_t smem_u32(const void* p) {
    uint32_t a;
    asm("{ .reg .u64 t; cvta.to.shared.u64 t, %1; cvt.u32.u64 %0, t; }" : "=r"(a) : "l"(p));
    return a;
}
__device__ __forceinline__ void cp16(uint32_t dst, const void* src) {
    asm volatile("cp.async.cg.shared.global [%0], [%1], 16;"
                 :: "r"(dst), "l"(__cvta_generic_to_global(src)) : "memory");
}
#define CP_COMMIT() asm volatile("cp.async.commit_group;" ::: "memory")
#define CP_WAIT(n)  asm volatile("cp.async.wait_group %0;" :: "n"(n) : "memory")

__device__ __forceinline__ void ldsm_x4(uint32_t (&r)[4], uint32_t addr) {
    asm volatile("ldmatrix.sync.aligned.m8n8.x4.shared.b16 {%0,%1,%2,%3}, [%4];"
                 : "=r"(r[0]), "=r"(r[1]), "=r"(r[2]), "=r"(r[3]) : "r"(addr));
}
__device__ __forceinline__ void ldsm_x4t(uint32_t (&r)[4], uint32_t addr) {
    asm volatile("ldmatrix.sync.aligned.m8n8.x4.trans.shared.b16 {%0,%1,%2,%3}, [%4];"
                 : "=r"(r[0]), "=r"(r[1]), "=r"(r[2]), "=r"(r[3]) : "r"(addr));
}
// f16 inputs, f16 accumulator, D += A*B
__device__ __forceinline__ void mma_h16_acc(uint32_t (&d)[2], const uint32_t (&a)[4],
                                            uint32_t b0, uint32_t b1) {
    asm volatile("mma.sync.aligned.m16n8k16.row.col.f16.f16.f16.f16 "
                 "{%0,%1}, {%2,%3,%4,%5}, {%6,%7}, {%0,%1};"
                 : "+r"(d[0]), "+r"(d[1])
                 : "r"(a[0]), "r"(a[1]), "r"(a[2]), "r"(a[3]), "r"(b0), "r"(b1));
}
// f16 inputs, f16 accumulator, D = A*B
__device__ __forceinline__ void mma_h16(uint32_t (&d)[2], const uint32_t (&a)[4],
                                        uint32_t b0, uint32_t b1) {
    asm volatile("mma.sync.aligned.m16n8k16.row.col.f16.f16.f16.f16 "
                 "{%0,%1}, {%2,%3,%4,%5}, {%6,%7}, {%8,%9};"
                 : "=r"(d[0]), "=r"(d[1])
                 : "r"(a[0]), "r"(a[1]), "r"(a[2]), "r"(a[3]),
                   "r"(b0), "r"(b1), "r"(0u), "r"(0u));
}
__device__ __forceinline__ __half2 shfl_h2(__half2 v, int m) {
    uint32_t u = *reinterpret_cast<uint32_t*>(&v);
    u = __shfl_xor_sync(0xffffffffu, u, m);
    return *reinterpret_cast<__half2*>(&u);
}

// ---------------------------------------------------------------------------
// Prep (pure elementwise, no transpose): 1M float4 tasks.
//   seg 0: drug -> g_abf[0]        seg 1: protein -> g_abf[1]
//   seg 2: Wd*(1/16) -> g_wbf[0]   seg 3: Wp -> g_wbf[1]   (k-major kept)
// ---------------------------------------------------------------------------
__global__ __launch_bounds__(256) void prep_kernel(
    const float* __restrict__ drug, const float* __restrict__ protein,
    const float* __restrict__ Wd, const float* __restrict__ Wp)
{
    int i = blockIdx.x * 256 + threadIdx.x;           // 0 .. 1M-1 (float4 index)
    int seg = i >> 18;                                 // 256K float4 per segment
    int j = i & 0x3FFFF;
    const float* src;
    __half* dst;
    float s = 1.0f;
    if (seg == 0)      { src = drug;    dst = g_abf[0]; }
    else if (seg == 1) { src = protein; dst = g_abf[1]; }
    else if (seg == 2) { src = Wd;      dst = g_wbf[0]; s = 0.0625f; }
    else               { src = Wp;      dst = g_wbf[1]; }
    float4 v = ((const float4*)src)[j];
    __half2 h0 = __floats2half2_rn(v.x * s, v.y * s);
    __half2 h1 = __floats2half2_rn(v.z * s, v.w * s);
    uint2 pk = make_uint2(*(uint32_t*)&h0, *(uint32_t*)&h1);
    ((uint2*)dst)[j] = pk;
}

// ---------------------------------------------------------------------------
// HMMA GEMM (f16 acc): CTA tile 128x128, 128 threads (4 warps, 2x2 grid),
// warp tile 64x64. A n-major (ldsm), B from k-major W (ldsm.trans).
// K = 4 chunks of 64, 2-stage cp.async, 64KB smem, 3 CTAs/SM.
// ---------------------------------------------------------------------------
#define GSMEM 65536

__global__ __launch_bounds__(128, 3) void gemm_tc_kernel(const float* __restrict__ b_d,
                                                         const float* __restrict__ b_p)
{
    extern __shared__ __align__(16) char dsm[];       // stage s: A @ s*32768, B @ s*32768+16384
    __shared__ __half2 bias2[64];

    const int tid = threadIdx.x, lane = tid & 31, w = tid >> 5;
    const int wm = w >> 1, wn = w & 1;                // 2x2 warp grid
    const int Nb = blockIdx.x * 128, Mb = blockIdx.y * 128, z = blockIdx.z;
    uint32_t sbase = smem_u32(dsm);

    const __half* Ag = g_abf[z];
    const __half* Wk = g_wbf[z];                      // [k][n], k-major
    if (tid < 64) {
        float s = z ? 1.0f : 0.0625f;
        const float* bias = z ? b_p : b_d;
        bias2[tid] = __floats2half2_rn(bias[Nb + 2 * tid] * s, bias[Nb + 2 * tid + 1] * s);
    }

    auto load_chunk = [&](int ch, int st) {
        uint32_t aB = sbase + st * 32768;
        uint32_t bB = aB + 16384;
#pragma unroll
        for (int j = 0; j < 8; j++) {
            int idx = tid + j * 128;                   // 0..1023
            // A: 128 rows (m) x 8 units (k)
            int ra = idx >> 3, ca = idx & 7;
            uint32_t swa = (uint32_t)(ra * 128 + ((ca ^ (ra & 7)) << 4));
            cp16(aB + swa, Ag + (size_t)(Mb + ra) * DEF + ch * 64 + ca * 8);
            // B: 64 rows (k) x 16 units (n)
            int rb = idx >> 4, cb = idx & 15;
            uint32_t swb = (uint32_t)(rb * 256 + ((cb ^ (rb & 7)) << 4));
            cp16(bB + swb, Wk + (size_t)(ch * 64 + rb) * NF + Nb + cb * 8);
        }
        CP_COMMIT();
    };

    load_chunk(0, 0);
    load_chunk(1, 1);

    uint32_t acc[4][8][2];
#pragma unroll
    for (int mf = 0; mf < 4; mf++)
#pragma unroll
        for (int nf = 0; nf < 8; nf++) { acc[mf][nf][0] = 0u; acc[mf][nf][1] = 0u; }

#pragma unroll
    for (int ch = 0; ch < 4; ch++) {
        if (ch == 3) { CP_WAIT(0); } else { CP_WAIT(1); }
        __syncthreads();
        uint32_t aBase = sbase + (ch & 1) * 32768;
        uint32_t bBase = aBase + 16384;
#pragma unroll
        for (int ks = 0; ks < 4; ks++) {
            uint32_t a[4][4];
#pragma unroll
            for (int mf = 0; mf < 4; mf++) {
                int r  = wm * 64 + mf * 16 + (lane & 7) + 8 * ((lane >> 3) & 1);
                int kc = ks * 2 + (lane >> 4);
                ldsm_x4(a[mf], aBase + r * 128 + ((kc ^ (r & 7)) << 4));
            }
            uint32_t bq[4][4];
#pragma unroll
            for (int g = 0; g < 4; g++) {
                // trans-ldsm on k-major B (same pattern as interact's P path)
                int kr = ks * 16 + (lane & 7) + 8 * ((lane >> 3) & 1);
                int nu = (wn * 64 + g * 16 + 8 * (lane >> 4)) >> 3;
                ldsm_x4t(bq[g], bBase + kr * 256 + ((nu ^ (kr & 7)) << 4));
            }
#pragma unroll
            for (int mf = 0; mf < 4; mf++)
#pragma unroll
                for (int nf = 0; nf < 8; nf++)
                    mma_h16_acc(acc[mf][nf], a[mf],
                                bq[nf >> 1][(nf & 1) * 2], bq[nf >> 1][(nf & 1) * 2 + 1]);
        }
        __syncthreads();
        if (ch + 2 < 4) load_chunk(ch + 2, ch & 1);
    }

    // epilogue: bias + relu in half2, staged via smem (XOR-swizzled), STG.128
    const __half2 z2 = __float2half2_rn(0.0f);
#pragma unroll
    for (int mf = 0; mf < 4; mf++) {
        int r0 = wm * 64 + mf * 16 + (lane >> 2);
        int r1 = r0 + 8;
#pragma unroll
        for (int nf = 0; nf < 8; nf++) {
            int u = wn * 8 + nf;                       // 16B unit within 256B row (0..15)
            __half2 b2 = bias2[u * 4 + (lane & 3)];
            __half2 h0 = __hmax2(__hadd2(*(__half2*)&acc[mf][nf][0], b2), z2);
            __half2 h1 = __hmax2(__hadd2(*(__half2*)&acc[mf][nf][1], b2), z2);
            uint32_t a0 = sbase + r0 * 256 + ((u ^ (r0 & 7)) << 4) + 4 * (lane & 3);
            uint32_t a1 = sbase + r1 * 256 + ((u ^ (r1 & 7)) << 4) + 4 * (lane & 3);
            asm volatile("st.shared.b32 [%0], %1;" :: "r"(a0), "r"(*(uint32_t*)&h0) : "memory");
            asm volatile("st.shared.b32 [%0], %1;" :: "r"(a1), "r"(*(uint32_t*)&h1) : "memory");
        }
    }
    __syncthreads();
#pragma unroll
    for (int p = 0; p < 16; p++) {
        int g = tid + p * 128;                         // 0..2047 16B units
        int row = g >> 4, u = g & 15;
        uint4 v;
        uint32_t ad = sbase + row * 256 + ((u ^ (row & 7)) << 4);
        asm volatile("ld.shared.v4.u32 {%0,%1,%2,%3}, [%4];"
                     : "=r"(v.x), "=r"(v.y), "=r"(v.z), "=r"(v.w) : "r"(ad));
        *(uint4*)&g_att[z][(size_t)(Mb + row) * NF + Nb + u * 8] = v;
    }
}

// ---------------------------------------------------------------------------
// Interaction: per-sample S = D(scaled) @ P via f16-acc HMMA (K=16).
// Row sums on the tensor pipe. min 7 CTAs/SM for latency hiding.
// ---------------------------------------------------------------------------
__global__ __launch_bounds__(256, 7) void interact_kernel(
    const float* __restrict__ drug, const float* __restrict__ protein,
    float* __restrict__ out)
{
    __shared__ __align__(16) char Dsm[256 * 48];      // D rows stride 48B (32B data + pad)
    __shared__ __align__(16) char Psm[16 * 512];      // P [16][256] f16, XOR-swizzled
    __shared__ __half2 colpart[8][128];
    __shared__ float rowsum[256];

    const int b = blockIdx.x, tid = threadIdx.x, lane = tid & 31, w = tid >> 5;
    uint32_t sD = smem_u32(Dsm), sP = smem_u32(Psm);
    const __half* Drow = g_att[0] + (size_t)b * NF;
    const __half* Prow = g_att[1] + (size_t)b * NF;

#pragma unroll
    for (int j = 0; j < 2; j++) {
        int idx = tid + j * 256;                       // 0..511, 16B chunks
        int r = idx >> 1, c = idx & 1;
        cp16(sD + r * 48 + c * 16, Drow + idx * 8);
        int h = idx >> 5, c2 = idx & 31;
        cp16(sP + h * 512 + ((c2 ^ (h & 7)) << 4), Prow + idx * 8);
    }
    CP_COMMIT(); CP_WAIT(0); __syncthreads();

    uint32_t a[2][4];
#pragma unroll
    for (int mf = 0; mf < 2; mf++) {
        int r  = w * 32 + mf * 16 + (lane & 7) + 8 * ((lane >> 3) & 1);
        int kc = lane >> 4;
        ldsm_x4(a[mf], sD + r * 48 + kc * 16);
    }

    const uint32_t ONES = 0x3C003C00u;                 // (1.0h, 1.0h)
    const __half2 zero2 = __float2half2_rn(0.0f);
    uint32_t rs[2][2] = {{0u, 0u}, {0u, 0u}};          // rowsum MMA accumulators

#pragma unroll
    for (int it = 0; it < 16; it++) {
        int n0 = it * 16;
        uint32_t bq[4];
        {
            int h = (lane & 7) + 8 * ((lane >> 3) & 1);
            int n = n0 + 8 * (lane >> 4);
            ldsm_x4t(bq, sP + h * 512 + (((n >> 3) ^ (h & 7)) << 4));
        }
        __half2 cp0 = zero2, cp1 = zero2;
#pragma unroll
        for (int mf = 0; mf < 2; mf++) {
            uint32_t d0[2], d1[2];
            mma_h16(d0, a[mf], bq[0], bq[1]);          // cols n0 + 2q
            mma_h16(d1, a[mf], bq[2], bq[3]);          // cols n0 + 8 + 2q
            uint32_t t[4];                             // tanh, in A-fragment layout
            t[0] = tanh_h2u(d0[0]);
            t[1] = tanh_h2u(d0[1]);
            t[2] = tanh_h2u(d1[0]);
            t[3] = tanh_h2u(d1[1]);
            // row sums on tensor pipe: rs += T(m16k16) @ ones(k16n8)
            mma_h16_acc(rs[mf], t, ONES, ONES);
            // col partials (sum over this warp's 32 rows)
            cp0 = __hadd2(cp0, __hadd2(*(__half2*)&t[0], *(__half2*)&t[1]));
            cp1 = __hadd2(cp1, __hadd2(*(__half2*)&t[2], *(__half2*)&t[3]));
        }
        cp0 = __hadd2(cp0, shfl_h2(cp0, 4));
        cp0 = __hadd2(cp0, shfl_h2(cp0, 8));
        cp0 = __hadd2(cp0, shfl_h2(cp0, 16));
        cp1 = __hadd2(cp1, shfl_h2(cp1, 4));
        cp1 = __hadd2(cp1, shfl_h2(cp1, 8));
        cp1 = __hadd2(cp1, shfl_h2(cp1, 16));
        if (lane < 4) {
            colpart[w][(n0 >> 1) + lane]     = cp0;
            colpart[w][(n0 >> 1) + 4 + lane] = cp1;
        }
    }

    // rowsum extraction: rs[mf] col 0 holds rowsum(row) (all cols identical)
    if ((lane & 3) == 0) {
#pragma unroll
        for (int mf = 0; mf < 2; mf++) {
            int row = w * 32 + mf * 16 + (lane >> 2);
            rowsum[row]     = __low2float(*(__half2*)&rs[mf][0]);
            rowsum[row + 8] = __low2float(*(__half2*)&rs[mf][1]);
        }
    }
    __syncthreads();

    size_t o = (size_t)b * DEF + tid;
    out[o] = drug[o] * tanh_fast(rowsum[tid]);

    if (tid < 128) {
        float c0 = 0.0f, c1 = 0.0f;
#pragma unroll
        for (int ww = 0; ww < 8; ww++) {
            __half2 v = colpart[ww][tid];
            c0 += __low2float(v);
            c1 += __high2float(v);
        }
        size_t base2 = (size_t)BSZ * DEF + (size_t)b * DEF + 2 * tid;
        out[base2]     = protein[(size_t)b * DEF + 2 * tid]     * tanh_fast(c0);
        out[base2 + 1] = protein[(size_t)b * DEF + 2 * tid + 1] * tanh_fast(c1);
    }
}

// ---------------------------------------------------------------------------
extern "C" void kernel_launch(void* const* d_in, const int* in_sizes, int n_in,
                              void* d_out, int out_size)
{
    const float* drug    = (const float*)d_in[0];
    const float* protein = (const float*)d_in[1];
    const float* W_d     = (const float*)d_in[2];
    const float* b_d     = (const float*)d_in[3];
    const float* W_p     = (const float*)d_in[4];
    const float* b_p     = (const float*)d_in[5];
    float* out = (float*)d_out;

    cudaFuncSetAttribute(gemm_tc_kernel, cudaFuncAttributeMaxDynamicSharedMemorySize, GSMEM);

    prep_kernel<<<4096, 256>>>(drug, protein, W_d, W_p);
    gemm_tc_kernel<<<dim3(NF / 128, BSZ / 128, 2), 128, GSMEM>>>(b_d, b_p);
    interact_kernel<<<BSZ, 256>>>(drug, protein, out);
}